// round 14
// baseline (speedup 1.0000x reference)
#include <cuda_runtime.h>
#include <cuda_bf16.h>
#include <cuda_fp16.h>
#include <math_constants.h>

#define N_NODES 50000
#define N_EDGES 600000
#define EE_MAX  (N_NODES + N_EDGES)
#define DIM     128
#define HEADS   4
#define NEG_SLOPE 0.2f

// ---------------- scratch (static device globals) ----------------
__device__ __half g_h   [(long long)N_NODES * DIM];   // h = X @ W, fp16
__device__ float g_out1 [(long long)N_NODES * DIM];
__device__ float g_als  [N_NODES * HEADS];
__device__ float g_ald  [N_NODES * HEADS];
__device__ int   g_deg  [N_NODES];      // INVARIANT: all-zero at entry to k_deg
                                        // (static init for call 1; k_scan re-zeroes)
__device__ int   g_rowptr[N_NODES + 1];
__device__ int   g_fill [N_NODES];
__device__ int   g_csr  [EE_MAX];

// ---------------- packed fp32x2 helpers ----------------
__device__ __forceinline__ void ffma2(unsigned long long& acc, unsigned long long a,
                                      unsigned long long b)
{
    asm("fma.rn.f32x2 %0, %1, %2, %0;" : "+l"(acc) : "l"(a), "l"(b));
}
__device__ __forceinline__ unsigned long long splat2(float x)
{
    unsigned long long r;
    asm("mov.b64 %0, {%1, %1};" : "=l"(r) : "f"(x));
    return r;
}
__device__ __forceinline__ void unpack2(unsigned long long v, float& a, float& b)
{
    asm("mov.b64 {%0, %1}, %2;" : "=f"(a), "=f"(b) : "l"(v));
}

// ---------------- GEMM + fused attention-logit reduction ----------------
template<int H>
__global__ void __launch_bounds__(256) k_gemm_al(
    const float* __restrict__ X, const float* __restrict__ W,
    const float* __restrict__ a_s, const float* __restrict__ a_d,
    __half* __restrict__ Hout, float* __restrict__ als, float* __restrict__ ald, int N)
{
    __shared__ float xs[32][DIM];
    const int tid = threadIdx.x;
    const int cg  = tid & 31;
    const int rs  = tid >> 5;          // warp id 0..7
    const int c0  = cg * 4;
    const int n0  = blockIdx.x * 32;

    for (int idx = tid; idx < 32 * (DIM / 4); idx += 256) {
        int r  = idx >> 5;             // 0..31
        int cc = (idx & 31) * 4;
        int n  = n0 + r;
        float4 v = make_float4(0.f, 0.f, 0.f, 0.f);
        if (n < N) v = *(const float4*)(X + (long long)n * DIM + cc);
        *(float4*)&xs[r][cc] = v;
    }
    __syncthreads();

    unsigned long long acc[4][2];
    #pragma unroll
    for (int r = 0; r < 4; r++) { acc[r][0] = 0ull; acc[r][1] = 0ull; }

    #pragma unroll 4
    for (int k = 0; k < DIM; k += 4) {
        ulonglong2 w0 = *(const ulonglong2*)(W + (k + 0) * DIM + c0);
        ulonglong2 w1 = *(const ulonglong2*)(W + (k + 1) * DIM + c0);
        ulonglong2 w2 = *(const ulonglong2*)(W + (k + 2) * DIM + c0);
        ulonglong2 w3 = *(const ulonglong2*)(W + (k + 3) * DIM + c0);
        #pragma unroll
        for (int r = 0; r < 4; r++) {
            float4 xv = *(const float4*)&xs[rs * 4 + r][k];
            unsigned long long x0 = splat2(xv.x), x1 = splat2(xv.y);
            unsigned long long x2 = splat2(xv.z), x3 = splat2(xv.w);
            ffma2(acc[r][0], w0.x, x0); ffma2(acc[r][1], w0.y, x0);
            ffma2(acc[r][0], w1.x, x1); ffma2(acc[r][1], w1.y, x1);
            ffma2(acc[r][0], w2.x, x2); ffma2(acc[r][1], w2.y, x2);
            ffma2(acc[r][0], w3.x, x3); ffma2(acc[r][1], w3.y, x3);
        }
    }

    const float4 as4 = *(const float4*)(a_s + c0);
    const float4 ad4 = *(const float4*)(a_d + c0);

    #pragma unroll
    for (int r = 0; r < 4; r++) {
        int n = n0 + rs * 4 + r;
        float a0, a1, a2, a3;
        unpack2(acc[r][0], a0, a1);
        unpack2(acc[r][1], a2, a3);
        if (n < N) {
            __half2 h01 = __floats2half2_rn(a0, a1);
            __half2 h23 = __floats2half2_rn(a2, a3);
            uint2 pk;
            pk.x = *reinterpret_cast<unsigned*>(&h01);
            pk.y = *reinterpret_cast<unsigned*>(&h23);
            *(uint2*)(Hout + (long long)n * DIM + c0) = pk;
        }
        float ss = a0 * as4.x + a1 * as4.y + a2 * as4.z + a3 * as4.w;
        float sd = a0 * ad4.x + a1 * ad4.y + a2 * ad4.z + a3 * ad4.w;
        #pragma unroll
        for (int o = (H == 4 ? 4 : 16); o > 0; o >>= 1) {
            ss += __shfl_xor_sync(0xffffffffu, ss, o);
            sd += __shfl_xor_sync(0xffffffffu, sd, o);
        }
        if (H == 4) {
            if ((cg & 7) == 0 && n < N) {
                int hh = cg >> 3;
                als[n * 4 + hh] = ss;
                ald[n * 4 + hh] = sd;
            }
        } else {
            if (cg == 0 && n < N) { als[n] = ss; ald[n] = sd; }
        }
    }
}

// ---------------- CSR build ----------------
// deg[] must be all-zero on entry (invariant maintained by k_scan).
__global__ void k_deg(const int* __restrict__ ei, int E, int* __restrict__ deg)
{
    int e4 = (blockIdx.x * blockDim.x + threadIdx.x) * 4;
    const int* dsts = ei + E;
    if (e4 + 3 < E) {
        int4 d = *(const int4*)(dsts + e4);
        atomicAdd(&deg[d.x], 1);
        atomicAdd(&deg[d.y], 1);
        atomicAdd(&deg[d.z], 1);
        atomicAdd(&deg[d.w], 1);
    } else {
        for (int e = e4; e < E; e++) atomicAdd(&deg[dsts[e]], 1);
    }
}
// Scan with implicit +1 per node (self-loop); zeroes deg[] for the next call.
__global__ void k_scan(int* __restrict__ deg, int* __restrict__ rowptr,
                       int* __restrict__ fill, int N)
{
    __shared__ int wsum[32];
    const int t = threadIdx.x;
    const int strip = (N + 1023) / 1024;
    const int lo = t * strip, hi = min(lo + strip, N);
    int s = 0;
    for (int i = lo; i < hi; i++) s += deg[i] + 1;

    const int lane = t & 31, wid = t >> 5;
    int v = s;
    #pragma unroll
    for (int o = 1; o < 32; o <<= 1) {
        int u = __shfl_up_sync(0xffffffffu, v, o);
        if (lane >= o) v += u;
    }
    if (lane == 31) wsum[wid] = v;
    __syncthreads();
    if (wid == 0) {
        int w = wsum[lane];
        #pragma unroll
        for (int o = 1; o < 32; o <<= 1) {
            int u = __shfl_up_sync(0xffffffffu, w, o);
            if (lane >= o) w += u;
        }
        wsum[lane] = w;
    }
    __syncthreads();
    int incl = v + (wid > 0 ? wsum[wid - 1] : 0);
    int base = incl - s;
    for (int i = lo; i < hi; i++) {
        int d = deg[i];
        deg[i] = 0;                     // restore invariant for next call
        rowptr[i] = base;
        fill[i]   = base;
        base += d + 1;
    }
    if (t == 1023) rowptr[N] = incl;
}
__global__ void k_fill(const int* __restrict__ ei, int E, int EE,
                       int* __restrict__ fill, int* __restrict__ csr)
{
    int e4 = (blockIdx.x * blockDim.x + threadIdx.x) * 4;
    if (e4 >= EE) return;
    if (e4 + 3 < E) {
        int4 s = *(const int4*)(ei + e4);
        int4 d = *(const int4*)(ei + E + e4);
        csr[atomicAdd(&fill[d.x], 1)] = s.x;
        csr[atomicAdd(&fill[d.y], 1)] = s.y;
        csr[atomicAdd(&fill[d.z], 1)] = s.z;
        csr[atomicAdd(&fill[d.w], 1)] = s.w;
    } else {
        for (int e = e4; e < min(e4 + 4, EE); e++) {
            int src, dst;
            if (e < E) { src = ei[e]; dst = ei[E + e]; } else { src = dst = e - E; }
            csr[atomicAdd(&fill[dst], 1)] = src;
        }
    }
}

// ---------------- fused single-pass gather aggregation (round-12 form) -------
template<int H, bool ELU>
__global__ void k_aggregate(const int* __restrict__ rowptr, const int* __restrict__ csr,
                            const float* __restrict__ als, const float* __restrict__ ald,
                            const __half* __restrict__ hbuf, const float* __restrict__ bias,
                            float* __restrict__ out, int N)
{
    int node = (blockIdx.x * blockDim.x + threadIdx.x) >> 5;
    if (node >= N) return;
    const int lane = threadIdx.x & 31;
    const int head = (H == 4) ? (lane >> 3) : 0;
    const int c0   = lane * 4;

    const int s = rowptr[node];
    const int t = rowptr[node + 1];
    const float adv = (H == 4) ? ald[node * 4 + head] : ald[node];

    float den = 0.f;
    float4 acc = make_float4(0.f, 0.f, 0.f, 0.f);

    int i = s;
    for (; i + 3 < t; i += 4) {
        int s0 = csr[i], s1 = csr[i + 1], s2 = csr[i + 2], s3 = csr[i + 3];
        float v0 = ((H == 4) ? als[s0 * 4 + head] : als[s0]) + adv;
        float v1 = ((H == 4) ? als[s1 * 4 + head] : als[s1]) + adv;
        float v2 = ((H == 4) ? als[s2 * 4 + head] : als[s2]) + adv;
        float v3 = ((H == 4) ? als[s3 * 4 + head] : als[s3]) + adv;
        v0 = v0 > 0.f ? v0 : NEG_SLOPE * v0;
        v1 = v1 > 0.f ? v1 : NEG_SLOPE * v1;
        v2 = v2 > 0.f ? v2 : NEG_SLOPE * v2;
        v3 = v3 > 0.f ? v3 : NEG_SLOPE * v3;
        float e0 = __expf(v0), e1 = __expf(v1), e2 = __expf(v2), e3 = __expf(v3);
        uint2 u0 = *(const uint2*)(hbuf + (long long)s0 * DIM + c0);
        uint2 u1 = *(const uint2*)(hbuf + (long long)s1 * DIM + c0);
        uint2 u2 = *(const uint2*)(hbuf + (long long)s2 * DIM + c0);
        uint2 u3 = *(const uint2*)(hbuf + (long long)s3 * DIM + c0);
        den += (e0 + e1) + (e2 + e3);
        float2 f0a = __half22float2(*reinterpret_cast<const __half2*>(&u0.x));
        float2 f0b = __half22float2(*reinterpret_cast<const __half2*>(&u0.y));
        float2 f1a = __half22float2(*reinterpret_cast<const __half2*>(&u1.x));
        float2 f1b = __half22float2(*reinterpret_cast<const __half2*>(&u1.y));
        float2 f2a = __half22float2(*reinterpret_cast<const __half2*>(&u2.x));
        float2 f2b = __half22float2(*reinterpret_cast<const __half2*>(&u2.y));
        float2 f3a = __half22float2(*reinterpret_cast<const __half2*>(&u3.x));
        float2 f3b = __half22float2(*reinterpret_cast<const __half2*>(&u3.y));
        acc.x = fmaf(f0a.x, e0, fmaf(f1a.x, e1, fmaf(f2a.x, e2, fmaf(f3a.x, e3, acc.x))));
        acc.y = fmaf(f0a.y, e0, fmaf(f1a.y, e1, fmaf(f2a.y, e2, fmaf(f3a.y, e3, acc.y))));
        acc.z = fmaf(f0b.x, e0, fmaf(f1b.x, e1, fmaf(f2b.x, e2, fmaf(f3b.x, e3, acc.z))));
        acc.w = fmaf(f0b.y, e0, fmaf(f1b.y, e1, fmaf(f2b.y, e2, fmaf(f3b.y, e3, acc.w))));
    }
    for (; i < t; i++) {
        int s0 = csr[i];
        float v0 = ((H == 4) ? als[s0 * 4 + head] : als[s0]) + adv;
        v0 = v0 > 0.f ? v0 : NEG_SLOPE * v0;
        float e0 = __expf(v0);
        uint2 u0 = *(const uint2*)(hbuf + (long long)s0 * DIM + c0);
        float2 f0a = __half22float2(*reinterpret_cast<const __half2*>(&u0.x));
        float2 f0b = __half22float2(*reinterpret_cast<const __half2*>(&u0.y));
        den += e0;
        acc.x = fmaf(f0a.x, e0, acc.x);
        acc.y = fmaf(f0a.y, e0, acc.y);
        acc.z = fmaf(f0b.x, e0, acc.z);
        acc.w = fmaf(f0b.y, e0, acc.w);
    }

    const float inv = 1.f / (den + 1e-16f);
    const float4 b4 = *(const float4*)(bias + c0);
    float4 o;
    o.x = acc.x * inv + b4.x;
    o.y = acc.y * inv + b4.y;
    o.z = acc.z * inv + b4.z;
    o.w = acc.w * inv + b4.w;
    if (ELU) {
        o.x = o.x > 0.f ? o.x : expm1f(o.x);
        o.y = o.y > 0.f ? o.y : expm1f(o.y);
        o.z = o.z > 0.f ? o.z : expm1f(o.z);
        o.w = o.w > 0.f ? o.w : expm1f(o.w);
    }
    *(float4*)(out + (long long)node * DIM + c0) = o;
}

// ---------------- launch ----------------
extern "C" void kernel_launch(void* const* d_in, const int* in_sizes, int n_in,
                              void* d_out, int out_size)
{
    const float* x   = (const float*)d_in[0];
    const int*   ei  = (const int*)d_in[1];
    const float* W1  = (const float*)d_in[2];
    const float* as1 = (const float*)d_in[3];
    const float* ad1 = (const float*)d_in[4];
    const float* b1  = (const float*)d_in[5];
    const float* W2  = (const float*)d_in[6];
    const float* as2 = (const float*)d_in[7];
    const float* ad2 = (const float*)d_in[8];
    const float* b2  = (const float*)d_in[9];
    float*       out = (float*)d_out;

    const int N  = in_sizes[0] / DIM;
    const int E  = in_sizes[1] / 2;
    const int EE = E + N;

    __half* h;
    float *out1, *als, *ald;
    int *deg, *rowptr, *fill, *csr;
    cudaGetSymbolAddress((void**)&h,      g_h);
    cudaGetSymbolAddress((void**)&out1,   g_out1);
    cudaGetSymbolAddress((void**)&als,    g_als);
    cudaGetSymbolAddress((void**)&ald,    g_ald);
    cudaGetSymbolAddress((void**)&deg,    g_deg);
    cudaGetSymbolAddress((void**)&rowptr, g_rowptr);
    cudaGetSymbolAddress((void**)&fill,   g_fill);
    cudaGetSymbolAddress((void**)&csr,    g_csr);

    static cudaStream_t s_side = nullptr;
    static cudaEvent_t  ev_fork = nullptr, ev_join = nullptr;
    if (s_side == nullptr) {
        cudaStreamCreateWithFlags(&s_side, cudaStreamNonBlocking);
        cudaEventCreateWithFlags(&ev_fork, cudaEventDisableTiming);
        cudaEventCreateWithFlags(&ev_join, cudaEventDisableTiming);
    }

    const int TB = 256;
    dim3 gWarp((unsigned)(((long long)N * 32 + TB - 1) / TB));
    dim3 gGemm((N + 31) / 32);

    // Fork: CSR build (3 kernels; deg_init eliminated via scan-zeroing
    // invariant) on side stream, concurrent with GEMM1 on main stream.
    cudaEventRecord(ev_fork, 0);
    cudaStreamWaitEvent(s_side, ev_fork, 0);

    k_deg<<<((E + 3) / 4 + TB - 1) / TB, TB, 0, s_side>>>(ei, E, deg);
    k_scan<<<1, 1024, 0, s_side>>>(deg, rowptr, fill, N);
    k_fill<<<((EE + 3) / 4 + TB - 1) / TB, TB, 0, s_side>>>(ei, E, EE, fill, csr);
    cudaEventRecord(ev_join, s_side);

    // GEMM1 on main stream (4th kernel launch -> lands in ncu's capture slot)
    k_gemm_al<4><<<gGemm, 256>>>(x, W1, as1, ad1, h, als, ald, N);

    // Join: aggregation needs both CSR and GEMM1
    cudaStreamWaitEvent(0, ev_join, 0);

    k_aggregate<4, true><<<gWarp, TB>>>(rowptr, csr, als, ald, h, b1, out1, N);

    // layer 2 (H=1)
    k_gemm_al<1><<<gGemm, 256>>>(out1, W2, as2, ad2, h, als, ald, N);
    k_aggregate<1, false><<<gWarp, TB>>>(rowptr, csr, als, ald, h, b2, out, N);
}

// round 15
// speedup vs baseline: 1.4481x; 1.4481x over previous
#include <cuda_runtime.h>
#include <cuda_bf16.h>
#include <cuda_fp16.h>
#include <math_constants.h>

#define N_NODES 50000
#define N_EDGES 600000
#define EE_MAX  (N_NODES + N_EDGES)
#define DIM     128
#define HEADS   4
#define NEG_SLOPE 0.2f

// ---------------- scratch (static device globals) ----------------
__device__ __half g_h    [(long long)N_NODES * DIM];  // h = X @ W (fp16)
__device__ __half g_out1h[(long long)N_NODES * DIM];  // layer-1 output (fp16, feeds GEMM2)
__device__ float g_als  [N_NODES * HEADS];
__device__ float g_ald  [N_NODES * HEADS];
__device__ int   g_deg  [N_NODES];      // INVARIANT: all-zero at entry (k_scan restores)
__device__ int   g_rowptr[N_NODES + 1];
__device__ int   g_fill [N_NODES];
__device__ int   g_csr  [EE_MAX];
__device__ uint4 g_w1frag[2048];        // W1 pre-packed into mma B-fragment layout
__device__ uint4 g_w2frag[2048];        // W2 likewise

__device__ __forceinline__ unsigned smem_u32(const void* p)
{
    unsigned a;
    asm("{ .reg .u64 t; cvta.to.shared.u64 t, %1; cvt.u32.u64 %0, t; }"
        : "=r"(a) : "l"(p));
    return a;
}

// ---------------- W -> B-fragment pre-pack ----------------
// Layout (u32 index): ((kt*2+nh)*4 + reg4)*128 + lane*4 + s ; j = reg4*4+s,
// nt = j>>1, breg = j&1.  Fragment: b = { W[k0][n], W[k0+1][n] },
// k0 = kt*16 + breg*8 + (lane&3)*2,  n = nh*64 + nt*8 + (lane>>2).
__global__ void k_wfrag(const float* __restrict__ W, unsigned* __restrict__ out)
{
    int tid = blockIdx.x * blockDim.x + threadIdx.x;
    if (tid >= 8192) return;
    int kt   = tid >> 10;
    int rem  = tid & 1023;
    int nh   = rem >> 9;
    int rem2 = rem & 511;
    int reg4 = rem2 >> 7;
    int rem3 = rem2 & 127;
    int lane = rem3 >> 2;
    int s    = rem3 & 3;
    int j    = reg4 * 4 + s;
    int nt   = j >> 1, breg = j & 1;
    int n    = nh * 64 + nt * 8 + (lane >> 2);
    int k0   = kt * 16 + breg * 8 + (lane & 3) * 2;
    __half2 p = __floats2half2_rn(W[k0 * DIM + n], W[(k0 + 1) * DIM + n]);
    out[tid] = *reinterpret_cast<unsigned*>(&p);
}

// ---------------- tensor-core GEMM + fused attention-logit reduction --------
// Block: 256 threads = 8 warps = 4 row-groups x 2 col-halves; 64 rows x 128 ch.
// Warp (rg, nh): rows rg*16..+15, cols nh*64..+63 (8 n-tiles of 8).
template<int H, bool AFP16>
__global__ void __launch_bounds__(256) k_gemm_mma(
    const void* __restrict__ Av, const uint4* __restrict__ Wfrag,
    const float* __restrict__ a_s, const float* __restrict__ a_d,
    __half* __restrict__ Hout, float* __restrict__ als, float* __restrict__ ald,
    int N)
{
    __shared__ __align__(16) __half Xs[64][136];   // padded: conflict-free ldmatrix
    __shared__ __align__(16) float als_s[64][4];
    __shared__ __align__(16) float ald_s[64][4];

    const int tid  = threadIdx.x;
    const int lane = tid & 31, warp = tid >> 5;
    const int rg   = warp >> 1, nh = warp & 1;
    const int n0   = blockIdx.x * 64;

    // ---- stage A tile (64 rows x 128 cols) into fp16 smem ----
    {
        int row   = tid >> 2;            // 0..63
        int cbase = (tid & 3) * 32;
        int n     = n0 + row;
        if (AFP16) {
            const __half* A = (const __half*)Av;
            #pragma unroll
            for (int i = 0; i < 4; i++) {
                int c = cbase + i * 8;
                uint4 v = make_uint4(0u, 0u, 0u, 0u);
                if (n < N) v = *(const uint4*)(A + (long long)n * DIM + c);
                *(uint4*)&Xs[row][c] = v;
            }
        } else {
            const float* A = (const float*)Av;
            #pragma unroll
            for (int i = 0; i < 8; i++) {
                int c = cbase + i * 4;
                float4 v = make_float4(0.f, 0.f, 0.f, 0.f);
                if (n < N) v = *(const float4*)(A + (long long)n * DIM + c);
                __half2 h01 = __floats2half2_rn(v.x, v.y);
                __half2 h23 = __floats2half2_rn(v.z, v.w);
                uint2 pk;
                pk.x = *reinterpret_cast<unsigned*>(&h01);
                pk.y = *reinterpret_cast<unsigned*>(&h23);
                *(uint2*)&Xs[row][c] = pk;
            }
        }
    }
    __syncthreads();

    float acc[8][4];
    #pragma unroll
    for (int t = 0; t < 8; t++)
        { acc[t][0] = 0.f; acc[t][1] = 0.f; acc[t][2] = 0.f; acc[t][3] = 0.f; }

    // ldmatrix row/col for this lane
    const int lrow = rg * 16 + (lane & 15);
    const int lcol = (lane >> 4) * 8;
    const unsigned abase = smem_u32(&Xs[lrow][lcol]);

    #pragma unroll
    for (int kt = 0; kt < 8; kt++) {
        unsigned a0, a1, a2, a3;
        asm volatile("ldmatrix.sync.aligned.m8n8.x4.shared.b16 {%0,%1,%2,%3}, [%4];"
                     : "=r"(a0), "=r"(a1), "=r"(a2), "=r"(a3)
                     : "r"(abase + kt * 32));

        const uint4* wp = Wfrag + ((kt * 2 + nh) * 4) * 32 + lane;
        uint4 q0 = wp[0];
        uint4 q1 = wp[32];
        uint4 q2 = wp[64];
        uint4 q3 = wp[96];

        #define MMA(ACC, B0, B1)                                                  \
            asm volatile("mma.sync.aligned.m16n8k16.row.col.f32.f16.f16.f32 "     \
                         "{%0,%1,%2,%3}, {%4,%5,%6,%7}, {%8,%9}, {%0,%1,%2,%3};"  \
                         : "+f"(ACC[0]), "+f"(ACC[1]), "+f"(ACC[2]), "+f"(ACC[3]) \
                         : "r"(a0), "r"(a1), "r"(a2), "r"(a3), "r"(B0), "r"(B1))
        MMA(acc[0], q0.x, q0.y);
        MMA(acc[1], q0.z, q0.w);
        MMA(acc[2], q1.x, q1.y);
        MMA(acc[3], q1.z, q1.w);
        MMA(acc[4], q2.x, q2.y);
        MMA(acc[5], q2.z, q2.w);
        MMA(acc[6], q3.x, q3.y);
        MMA(acc[7], q3.z, q3.w);
        #undef MMA
    }

    // ---- epilogue: h store (fp16) + logit partials from fp32 accumulators ----
    const int g  = lane >> 2, t2 = (lane & 3) * 2;
    const int r0 = rg * 16 + g, r1 = r0 + 8;
    const int nr0 = n0 + r0, nr1 = n0 + r1;

    float ps[2][2] = {{0.f, 0.f}, {0.f, 0.f}};   // [head-half][row0/row1]
    float pd[2][2] = {{0.f, 0.f}, {0.f, 0.f}};

    #pragma unroll
    for (int nt = 0; nt < 8; nt++) {
        int col = nh * 64 + nt * 8 + t2;
        float2 as2 = *(const float2*)(a_s + col);
        float2 ad2 = *(const float2*)(a_d + col);
        int hh = nt >> 2;
        ps[hh][0] += acc[nt][0] * as2.x + acc[nt][1] * as2.y;
        ps[hh][1] += acc[nt][2] * as2.x + acc[nt][3] * as2.y;
        pd[hh][0] += acc[nt][0] * ad2.x + acc[nt][1] * ad2.y;
        pd[hh][1] += acc[nt][2] * ad2.x + acc[nt][3] * ad2.y;
        __half2 h0 = __floats2half2_rn(acc[nt][0], acc[nt][1]);
        __half2 h1 = __floats2half2_rn(acc[nt][2], acc[nt][3]);
        if (nr0 < N)
            *(unsigned*)(Hout + (long long)nr0 * DIM + col) = *reinterpret_cast<unsigned*>(&h0);
        if (nr1 < N)
            *(unsigned*)(Hout + (long long)nr1 * DIM + col) = *reinterpret_cast<unsigned*>(&h1);
    }

    // quad (4-lane) reduction of the 8 partials
    #pragma unroll
    for (int o = 1; o <= 2; o <<= 1) {
        #pragma unroll
        for (int hh = 0; hh < 2; hh++) {
            #pragma unroll
            for (int rr = 0; rr < 2; rr++) {
                ps[hh][rr] += __shfl_xor_sync(0xffffffffu, ps[hh][rr], o);
                pd[hh][rr] += __shfl_xor_sync(0xffffffffu, pd[hh][rr], o);
            }
        }
    }
    if ((lane & 3) == 0) {
        als_s[r0][2 * nh + 0] = ps[0][0];
        als_s[r0][2 * nh + 1] = ps[1][0];
        als_s[r1][2 * nh + 0] = ps[0][1];
        als_s[r1][2 * nh + 1] = ps[1][1];
        ald_s[r0][2 * nh + 0] = pd[0][0];
        ald_s[r0][2 * nh + 1] = pd[1][0];
        ald_s[r1][2 * nh + 0] = pd[0][1];
        ald_s[r1][2 * nh + 1] = pd[1][1];
    }
    __syncthreads();

    if (tid < 64) {
        int n = n0 + tid;
        if (n < N) {
            float4 vs = *(const float4*)&als_s[tid][0];
            float4 vd = *(const float4*)&ald_s[tid][0];
            if (H == 4) {
                *(float4*)(als + n * 4) = vs;
                *(float4*)(ald + n * 4) = vd;
            } else {
                als[n] = (vs.x + vs.y) + (vs.z + vs.w);
                ald[n] = (vd.x + vd.y) + (vd.z + vd.w);
            }
        }
    }
}

// ---------------- CSR build ----------------
__global__ void k_deg(const int* __restrict__ ei, int E, int* __restrict__ deg)
{
    int e4 = (blockIdx.x * blockDim.x + threadIdx.x) * 4;
    const int* dsts = ei + E;
    if (e4 + 3 < E) {
        int4 d = *(const int4*)(dsts + e4);
        atomicAdd(&deg[d.x], 1);
        atomicAdd(&deg[d.y], 1);
        atomicAdd(&deg[d.z], 1);
        atomicAdd(&deg[d.w], 1);
    } else {
        for (int e = e4; e < E; e++) atomicAdd(&deg[dsts[e]], 1);
    }
}
__global__ void k_scan(int* __restrict__ deg, int* __restrict__ rowptr,
                       int* __restrict__ fill, int N)
{
    __shared__ int wsum[32];
    const int t = threadIdx.x;
    const int strip = (N + 1023) / 1024;
    const int lo = t * strip, hi = min(lo + strip, N);
    int s = 0;
    for (int i = lo; i < hi; i++) s += deg[i] + 1;   // +1 self-loop

    const int lane = t & 31, wid = t >> 5;
    int v = s;
    #pragma unroll
    for (int o = 1; o < 32; o <<= 1) {
        int u = __shfl_up_sync(0xffffffffu, v, o);
        if (lane >= o) v += u;
    }
    if (lane == 31) wsum[wid] = v;
    __syncthreads();
    if (wid == 0) {
        int w = wsum[lane];
        #pragma unroll
        for (int o = 1; o < 32; o <<= 1) {
            int u = __shfl_up_sync(0xffffffffu, w, o);
            if (lane >= o) w += u;
        }
        wsum[lane] = w;
    }
    __syncthreads();
    int incl = v + (wid > 0 ? wsum[wid - 1] : 0);
    int base = incl - s;
    for (int i = lo; i < hi; i++) {
        int d = deg[i];
        deg[i] = 0;                     // restore invariant
        rowptr[i] = base;
        fill[i]   = base;
        base += d + 1;
    }
    if (t == 1023) rowptr[N] = incl;
}
__global__ void k_fill(const int* __restrict__ ei, int E, int EE,
                       int* __restrict__ fill, int* __restrict__ csr)
{
    int e4 = (blockIdx.x * blockDim.x + threadIdx.x) * 4;
    if (e4 >= EE) return;
    if (e4 + 3 < E) {
        int4 s = *(const int4*)(ei + e4);
        int4 d = *(const int4*)(ei + E + e4);
        csr[atomicAdd(&fill[d.x], 1)] = s.x;
        csr[atomicAdd(&fill[d.y], 1)] = s.y;
        csr[atomicAdd(&fill[d.z], 1)] = s.z;
        csr[atomicAdd(&fill[d.w], 1)] = s.w;
    } else {
        for (int e = e4; e < min(e4 + 4, EE); e++) {
            int src, dst;
            if (e < E) { src = ei[e]; dst = ei[E + e]; } else { src = dst = e - E; }
            csr[atomicAdd(&fill[dst], 1)] = src;
        }
    }
}

// ---------------- fused single-pass gather aggregation ----------------
// One warp per destination node; lane -> 4 channels; h gathered fp16.
// OUTH: write fp16 (feeds layer-2 tensor GEMM) vs fp32 (final output).
template<int H, bool ELU, bool OUTH>
__global__ void k_aggregate(const int* __restrict__ rowptr, const int* __restrict__ csr,
                            const float* __restrict__ als, const float* __restrict__ ald,
                            const __half* __restrict__ hbuf, const float* __restrict__ bias,
                            void* __restrict__ outv, int N)
{
    int node = (blockIdx.x * blockDim.x + threadIdx.x) >> 5;
    if (node >= N) return;
    const int lane = threadIdx.x & 31;
    const int head = (H == 4) ? (lane >> 3) : 0;
    const int c0   = lane * 4;

    const int s = rowptr[node];
    const int t = rowptr[node + 1];
    const float adv = (H == 4) ? ald[node * 4 + head] : ald[node];

    float den = 0.f;
    float4 acc = make_float4(0.f, 0.f, 0.f, 0.f);

    int i = s;
    for (; i + 3 < t; i += 4) {
        int s0 = csr[i], s1 = csr[i + 1], s2 = csr[i + 2], s3 = csr[i + 3];
        float v0 = ((H == 4) ? als[s0 * 4 + head] : als[s0]) + adv;
        float v1 = ((H == 4) ? als[s1 * 4 + head] : als[s1]) + adv;
        float v2 = ((H == 4) ? als[s2 * 4 + head] : als[s2]) + adv;
        float v3 = ((H == 4) ? als[s3 * 4 + head] : als[s3]) + adv;
        v0 = v0 > 0.f ? v0 : NEG_SLOPE * v0;
        v1 = v1 > 0.f ? v1 : NEG_SLOPE * v1;
        v2 = v2 > 0.f ? v2 : NEG_SLOPE * v2;
        v3 = v3 > 0.f ? v3 : NEG_SLOPE * v3;
        float e0 = __expf(v0), e1 = __expf(v1), e2 = __expf(v2), e3 = __expf(v3);
        uint2 u0 = *(const uint2*)(hbuf + (long long)s0 * DIM + c0);
        uint2 u1 = *(const uint2*)(hbuf + (long long)s1 * DIM + c0);
        uint2 u2 = *(const uint2*)(hbuf + (long long)s2 * DIM + c0);
        uint2 u3 = *(const uint2*)(hbuf + (long long)s3 * DIM + c0);
        den += (e0 + e1) + (e2 + e3);
        float2 f0a = __half22float2(*reinterpret_cast<const __half2*>(&u0.x));
        float2 f0b = __half22float2(*reinterpret_cast<const __half2*>(&u0.y));
        float2 f1a = __half22float2(*reinterpret_cast<const __half2*>(&u1.x));
        float2 f1b = __half22float2(*reinterpret_cast<const __half2*>(&u1.y));
        float2 f2a = __half22float2(*reinterpret_cast<const __half2*>(&u2.x));
        float2 f2b = __half22float2(*reinterpret_cast<const __half2*>(&u2.y));
        float2 f3a = __half22float2(*reinterpret_cast<const __half2*>(&u3.x));
        float2 f3b = __half22float2(*reinterpret_cast<const __half2*>(&u3.y));
        acc.x = fmaf(f0a.x, e0, fmaf(f1a.x, e1, fmaf(f2a.x, e2, fmaf(f3a.x, e3, acc.x))));
        acc.y = fmaf(f0a.y, e0, fmaf(f1a.y, e1, fmaf(f2a.y, e2, fmaf(f3a.y, e3, acc.y))));
        acc.z = fmaf(f0b.x, e0, fmaf(f1b.x, e1, fmaf(f2b.x, e2, fmaf(f3b.x, e3, acc.z))));
        acc.w = fmaf(f0b.y, e0, fmaf(f1b.y, e1, fmaf(f2b.y, e2, fmaf(f3b.y, e3, acc.w))));
    }
    for (; i < t; i++) {
        int s0 = csr[i];
        float v0 = ((H == 4) ? als[s0 * 4 + head] : als[s0]) + adv;
        v0 = v0 > 0.f ? v0 : NEG_SLOPE * v0;
        float e0 = __expf(v0);
        uint2 u0 = *(const uint2*)(hbuf + (long long)s0 * DIM + c0);
        float2 f0a = __half22float2(*reinterpret_cast<const __half2*>(&u0.x));
        float2 f0b = __half22float2(*reinterpret_cast<const __half2*>(&u0.y));
        den += e0;
        acc.x = fmaf(f0a.x, e0, acc.x);
        acc.y = fmaf(f0a.y, e0, acc.y);
        acc.z = fmaf(f0b.x, e0, acc.z);
        acc.w = fmaf(f0b.y, e0, acc.w);
    }

    const float inv = 1.f / (den + 1e-16f);
    const float4 b4 = *(const float4*)(bias + c0);
    float4 o;
    o.x = acc.x * inv + b4.x;
    o.y = acc.y * inv + b4.y;
    o.z = acc.z * inv + b4.z;
    o.w = acc.w * inv + b4.w;
    if (ELU) {
        o.x = o.x > 0.f ? o.x : expm1f(o.x);
        o.y = o.y > 0.f ? o.y : expm1f(o.y);
        o.z = o.z > 0.f ? o.z : expm1f(o.z);
        o.w = o.w > 0.f ? o.w : expm1f(o.w);
    }
    if (OUTH) {
        __half2 h01 = __floats2half2_rn(o.x, o.y);
        __half2 h23 = __floats2half2_rn(o.z, o.w);
        uint2 pk;
        pk.x = *reinterpret_cast<unsigned*>(&h01);
        pk.y = *reinterpret_cast<unsigned*>(&h23);
        *(uint2*)((__half*)outv + (long long)node * DIM + c0) = pk;
    } else {
        *(float4*)((float*)outv + (long long)node * DIM + c0) = o;
    }
}

// ---------------- launch ----------------
extern "C" void kernel_launch(void* const* d_in, const int* in_sizes, int n_in,
                              void* d_out, int out_size)
{
    const float* x   = (const float*)d_in[0];
    const int*   ei  = (const int*)d_in[1];
    const float* W1  = (const float*)d_in[2];
    const float* as1 = (const float*)d_in[3];
    const float* ad1 = (const float*)d_in[4];
    const float* b1  = (const float*)d_in[5];
    const float* W2  = (const float*)d_in[6];
    const float* as2 = (const float*)d_in[7];
    const float* ad2 = (const float*)d_in[8];
    const float* b2  = (const float*)d_in[9];
    float*       out = (float*)d_out;

    const int N  = in_sizes[0] / DIM;
    const int E  = in_sizes[1] / 2;
    const int EE = E + N;

    __half *h, *out1h;
    float *als, *ald;
    int *deg, *rowptr, *fill, *csr;
    uint4 *w1f, *w2f;
    cudaGetSymbolAddress((void**)&h,      g_h);
    cudaGetSymbolAddress((void**)&out1h,  g_out1h);
    cudaGetSymbolAddress((void**)&als,    g_als);
    cudaGetSymbolAddress((void**)&ald,    g_ald);
    cudaGetSymbolAddress((void**)&deg,    g_deg);
    cudaGetSymbolAddress((void**)&rowptr, g_rowptr);
    cudaGetSymbolAddress((void**)&fill,   g_fill);
    cudaGetSymbolAddress((void**)&csr,    g_csr);
    cudaGetSymbolAddress((void**)&w1f,    g_w1frag);
    cudaGetSymbolAddress((void**)&w2f,    g_w2frag);

    static cudaStream_t s_side = nullptr;
    static cudaEvent_t  ev_fork = nullptr, ev_join = nullptr;
    if (s_side == nullptr) {
        cudaStreamCreateWithFlags(&s_side, cudaStreamNonBlocking);
        cudaEventCreateWithFlags(&ev_fork, cudaEventDisableTiming);
        cudaEventCreateWithFlags(&ev_join, cudaEventDisableTiming);
    }

    const int TB = 256;
    dim3 gWarp((unsigned)(((long long)N * 32 + TB - 1) / TB));
    dim3 gGemm((N + 63) / 64);

    // Fork: CSR build on side stream, concurrent with W-pack + GEMM1.
    cudaEventRecord(ev_fork, 0);
    cudaStreamWaitEvent(s_side, ev_fork, 0);

    k_deg<<<((E + 3) / 4 + TB - 1) / TB, TB, 0, s_side>>>(ei, E, deg);
    k_scan<<<1, 1024, 0, s_side>>>(deg, rowptr, fill, N);
    k_fill<<<((EE + 3) / 4 + TB - 1) / TB, TB, 0, s_side>>>(ei, E, EE, fill, csr);
    cudaEventRecord(ev_join, s_side);

    // Main stream: pack both W matrices, then layer-1 tensor GEMM
    k_wfrag<<<32, 256>>>(W1, (unsigned*)w1f);
    k_wfrag<<<32, 256>>>(W2, (unsigned*)w2f);
    k_gemm_mma<4, false><<<gGemm, 256>>>(x, w1f, as1, ad1, h, als, ald, N);

    // Join: aggregation needs both CSR and GEMM1
    cudaStreamWaitEvent(0, ev_join, 0);

    k_aggregate<4, true, true><<<gWarp, TB>>>(rowptr, csr, als, ald, h, b1, out1h, N);

    // layer 2 (H=1): fp16 input from aggregate
    k_gemm_mma<1, true><<<gGemm, 256>>>(out1h, w2f, as2, ad2, h, als, ald, N);
    k_aggregate<1, false, false><<<gWarp, TB>>>(rowptr, csr, als, ald, h, b2, out, N);
}